// round 1
// baseline (speedup 1.0000x reference)
#include <cuda_runtime.h>
#include <cstddef>

#define NN 512
#define MM 2048
#define FF 1024
#define GG 16
#define DD 64

// -------- scratch (static device allocations; allowed by harness rules) ----
__device__ float g_Q[NN * FF];                 // Q' = roi@Wq^T + Wq_b + u   [n][g*64+d]
__device__ float g_K[MM * FF];                 // K  = ref@Wk^T + Wk_b       [m][g*64+d]
__device__ float g_V[MM * FF];                 // V  = ref@Wv^T + Wv_b       [m][g*64+d]
__device__ float g_L[(size_t)NN * GG * MM];    // logits / attn              [n][g][m]

// freq[f] = 100 * 1000^(-f/8)  (double-precision derived constants)
__constant__ float c_freq[8] = {
    100.0f,        42.16965034f, 17.78279410f, 7.498942093f,
    3.162277660f,  1.333521432f, 0.5623413252f, 0.2371373706f};

// ===========================================================================
// C[i,j] = alpha * sum_c A[i,c]*B[j,c]  (+ bias0[j] + bias1[j])
// A:[I,lda] row-major, B:[J,ldb] row-major. 64x64 tile, BK=16, 4x4/thread.
// Batched via blockIdx.z with element strides bsA/bsB/bsC.
// All dims must be multiples of tile sizes (they are for this problem).
// ===========================================================================
__global__ void __launch_bounds__(256) gemm_nt_kernel(
    const float* __restrict__ A, int lda, int bsA,
    const float* __restrict__ B, int ldb, int bsB,
    float* __restrict__ C, int ldc, int bsC,
    int Kdim, float alpha,
    const float* __restrict__ bias0, const float* __restrict__ bias1)
{
    __shared__ float As[16][68];
    __shared__ float Bs[16][68];
    const int t = threadIdx.x;
    const float* Ab = A + (size_t)blockIdx.z * bsA;
    const float* Bb = B + (size_t)blockIdx.z * bsB;
    float* Cb = C + (size_t)blockIdx.z * bsC;
    const int i0 = blockIdx.y * 64;
    const int j0 = blockIdx.x * 64;
    const int lrow = t >> 2;           // 0..63
    const int lcol = (t & 3) << 2;     // 0,4,8,12
    const int tx = t & 15, ty = t >> 4;

    float acc[4][4];
#pragma unroll
    for (int a = 0; a < 4; a++)
#pragma unroll
        for (int b = 0; b < 4; b++) acc[a][b] = 0.f;

    for (int k0 = 0; k0 < Kdim; k0 += 16) {
        float4 av = *(const float4*)(Ab + (size_t)(i0 + lrow) * lda + k0 + lcol);
        float4 bv = *(const float4*)(Bb + (size_t)(j0 + lrow) * ldb + k0 + lcol);
        As[lcol + 0][lrow] = av.x; As[lcol + 1][lrow] = av.y;
        As[lcol + 2][lrow] = av.z; As[lcol + 3][lrow] = av.w;
        Bs[lcol + 0][lrow] = bv.x; Bs[lcol + 1][lrow] = bv.y;
        Bs[lcol + 2][lrow] = bv.z; Bs[lcol + 3][lrow] = bv.w;
        __syncthreads();
#pragma unroll
        for (int k = 0; k < 16; k++) {
            float4 a4 = *(const float4*)&As[k][ty << 2];
            float4 b4 = *(const float4*)&Bs[k][tx << 2];
            float aa[4] = {a4.x, a4.y, a4.z, a4.w};
            float bb[4] = {b4.x, b4.y, b4.z, b4.w};
#pragma unroll
            for (int ii = 0; ii < 4; ii++)
#pragma unroll
                for (int jj = 0; jj < 4; jj++)
                    acc[ii][jj] = fmaf(aa[ii], bb[jj], acc[ii][jj]);
        }
        __syncthreads();
    }

#pragma unroll
    for (int ii = 0; ii < 4; ii++) {
        int i = i0 + (ty << 2) + ii;
#pragma unroll
        for (int jj = 0; jj < 4; jj++) {
            int j = j0 + (tx << 2) + jj;
            float v = acc[ii][jj] * alpha;
            if (bias0) v += bias0[j];
            if (bias1) v += bias1[j];
            Cb[(size_t)i * ldc + j] = v;
        }
    }
}

// ===========================================================================
// C[i,j] += sum_{c in chunk} A[i,c]*B[c,j]   (atomic, split-k)
// A:[I,lda] row-major, B:[C,ldb] row-major (j contiguous). J tile = 64 (j0=0).
// ===========================================================================
__global__ void __launch_bounds__(256) gemm_nn_atomic_kernel(
    const float* __restrict__ A, int lda, int bsA,
    const float* __restrict__ B, int ldb, int bsB,
    float* __restrict__ C, int ldc, int bsC,
    int cChunk)
{
    __shared__ float As[16][68];
    __shared__ float Bs[16][68];
    const int t = threadIdx.x;
    const float* Ab = A + (size_t)blockIdx.z * bsA;
    const float* Bb = B + (size_t)blockIdx.z * bsB;
    float* Cb = C + (size_t)blockIdx.z * bsC;
    const int i0 = blockIdx.x * 64;
    const int c0 = blockIdx.y * cChunk;
    const int lrow = t >> 2;
    const int lcol = (t & 3) << 2;
    const int brow = t >> 4;           // 0..15
    const int bcol = (t & 15) << 2;    // 0..60
    const int tx = t & 15, ty = t >> 4;

    float acc[4][4];
#pragma unroll
    for (int a = 0; a < 4; a++)
#pragma unroll
        for (int b = 0; b < 4; b++) acc[a][b] = 0.f;

    for (int kk = 0; kk < cChunk; kk += 16) {
        float4 av = *(const float4*)(Ab + (size_t)(i0 + lrow) * lda + c0 + kk + lcol);
        float4 bv = *(const float4*)(Bb + (size_t)(c0 + kk + brow) * ldb + bcol);
        As[lcol + 0][lrow] = av.x; As[lcol + 1][lrow] = av.y;
        As[lcol + 2][lrow] = av.z; As[lcol + 3][lrow] = av.w;
        *(float4*)&Bs[brow][bcol] = bv;
        __syncthreads();
#pragma unroll
        for (int k = 0; k < 16; k++) {
            float4 a4 = *(const float4*)&As[k][ty << 2];
            float4 b4 = *(const float4*)&Bs[k][tx << 2];
            float aa[4] = {a4.x, a4.y, a4.z, a4.w};
            float bb[4] = {b4.x, b4.y, b4.z, b4.w};
#pragma unroll
            for (int ii = 0; ii < 4; ii++)
#pragma unroll
                for (int jj = 0; jj < 4; jj++)
                    acc[ii][jj] = fmaf(aa[ii], bb[jj], acc[ii][jj]);
        }
        __syncthreads();
    }

#pragma unroll
    for (int ii = 0; ii < 4; ii++)
#pragma unroll
        for (int jj = 0; jj < 4; jj++)
            atomicAdd(Cb + (size_t)(i0 + (ty << 2) + ii) * ldc + (tx << 2) + jj,
                      acc[ii][jj]);
}

// ===========================================================================
// For each (n, m): sinusoidal position embedding (64 dims), dot with Wg (16
// heads), relu, log(+1e-6), add scaled affinity already sitting in g_L.
// One thread per (n, m). blockIdx.y = n, blockIdx.x*256+tid = m.
// ===========================================================================
__global__ void __launch_bounds__(256) pos_logits_kernel(
    const float* __restrict__ bbox, const float* __restrict__ ref_bbox,
    const float* __restrict__ Wg_w, const float* __restrict__ Wg_b)
{
    __shared__ float sWsin[32][16];  // [c*8+f][g]
    __shared__ float sWcos[32][16];
    __shared__ float sWb[16];
    const int t = threadIdx.x;
    for (int idx = t; idx < 512; idx += 256) {
        int g = idx & 15;
        int cf = idx >> 4;           // c*8+f
        int c = cf >> 3, f = cf & 7;
        sWsin[cf][g] = Wg_w[g * 64 + c * 16 + f];
        sWcos[cf][g] = Wg_w[g * 64 + c * 16 + 8 + f];
    }
    if (t < 16) sWb[t] = Wg_b[t];
    __syncthreads();

    const int n = blockIdx.y;
    const int m = blockIdx.x * 256 + t;

    // per-n geometry (broadcast loads)
    float x0 = bbox[n * 4 + 0], y0 = bbox[n * 4 + 1];
    float x1 = bbox[n * 4 + 2], y1 = bbox[n * 4 + 3];
    float w = x1 - x0 + 1.f, h = y1 - y0 + 1.f;
    float cx = 0.5f * (x0 + x1), cy = 0.5f * (y0 + y1);
    float iw = 1.f / w, ih = 1.f / h;
    float lw = __logf(w), lh = __logf(h);

    // per-m geometry
    float4 rb = *(const float4*)(ref_bbox + (size_t)m * 4);
    float wr = rb.z - rb.x + 1.f, hr = rb.w - rb.y + 1.f;
    float cxr = 0.5f * (rb.x + rb.z), cyr = 0.5f * (rb.y + rb.w);

    float p[4];
    p[0] = __logf(fabsf((cx - cxr) * iw) + 1e-3f);
    p[1] = __logf(fabsf((cy - cyr) * ih) + 1e-3f);
    p[2] = lw - __logf(wr);
    p[3] = lh - __logf(hr);

    float acc[16];
#pragma unroll
    for (int g = 0; g < 16; g++) acc[g] = 0.f;

#pragma unroll
    for (int c = 0; c < 4; c++) {
#pragma unroll
        for (int f = 0; f < 8; f++) {
            float ang = p[c] * c_freq[f];
            float s = __sinf(ang);
            float co = __cosf(ang);
            const int cf = c * 8 + f;
#pragma unroll
            for (int g = 0; g < 16; g += 4) {
                float4 ws = *(const float4*)&sWsin[cf][g];
                float4 wc = *(const float4*)&sWcos[cf][g];
                acc[g + 0] = fmaf(s, ws.x, fmaf(co, wc.x, acc[g + 0]));
                acc[g + 1] = fmaf(s, ws.y, fmaf(co, wc.y, acc[g + 1]));
                acc[g + 2] = fmaf(s, ws.z, fmaf(co, wc.z, acc[g + 2]));
                acc[g + 3] = fmaf(s, ws.w, fmaf(co, wc.w, acc[g + 3]));
            }
        }
    }

    float* Lrow = g_L + (size_t)n * GG * MM + m;
#pragma unroll
    for (int g = 0; g < 16; g++) {
        float val = fmaxf(acc[g] + sWb[g], 0.f);
        float aff = Lrow[(size_t)g * MM];                 // already *0.125, +u·k
        Lrow[(size_t)g * MM] = __logf(val + 1e-6f) + aff;
    }
}

// ===========================================================================
// Row softmax over m (2048) per (n,g) row. In-place on g_L. One block / row.
// ===========================================================================
__global__ void __launch_bounds__(256) softmax_kernel()
{
    __shared__ float red[8];
    const int t = threadIdx.x;
    float* Lr = g_L + (size_t)blockIdx.x * MM;

    float v[8];
    float mx = -1e30f;
#pragma unroll
    for (int i = 0; i < 8; i++) {
        v[i] = Lr[t + i * 256];
        mx = fmaxf(mx, v[i]);
    }
#pragma unroll
    for (int o = 16; o > 0; o >>= 1) mx = fmaxf(mx, __shfl_xor_sync(~0u, mx, o));
    if ((t & 31) == 0) red[t >> 5] = mx;
    __syncthreads();
    float bm = red[0];
#pragma unroll
    for (int i = 1; i < 8; i++) bm = fmaxf(bm, red[i]);
    __syncthreads();

    float sum = 0.f;
#pragma unroll
    for (int i = 0; i < 8; i++) {
        v[i] = __expf(v[i] - bm);
        sum += v[i];
    }
#pragma unroll
    for (int o = 16; o > 0; o >>= 1) sum += __shfl_xor_sync(~0u, sum, o);
    if ((t & 31) == 0) red[t >> 5] = sum;
    __syncthreads();
    float bs = 0.f;
#pragma unroll
    for (int i = 0; i < 8; i++) bs += red[i];
    float inv = 1.f / bs;
#pragma unroll
    for (int i = 0; i < 8; i++) Lr[t + i * 256] = v[i] * inv;
}

// ===========================================================================
extern "C" void kernel_launch(void* const* d_in, const int* in_sizes, int n_in,
                              void* d_out, int out_size)
{
    (void)in_sizes; (void)n_in; (void)out_size;
    const float* bbox     = (const float*)d_in[0];
    const float* ref_bbox = (const float*)d_in[1];
    const float* roi_feat = (const float*)d_in[2];
    const float* ref_feat = (const float*)d_in[3];
    const float* Wg_w     = (const float*)d_in[4];
    const float* Wg_b     = (const float*)d_in[5];
    const float* Wq_w     = (const float*)d_in[6];
    const float* Wq_b     = (const float*)d_in[7];
    const float* Wk_w     = (const float*)d_in[8];
    const float* Wk_b     = (const float*)d_in[9];
    const float* Wv_w     = (const float*)d_in[10];  // [16,64,1024] == [1024,1024]
    const float* Wv_b     = (const float*)d_in[11];
    const float* u        = (const float*)d_in[12];  // [16,1,64] == [1024]
    float* out = (float*)d_out;

    float *Qd, *Kd, *Vd, *Ld;
    cudaGetSymbolAddress((void**)&Qd, g_Q);
    cudaGetSymbolAddress((void**)&Kd, g_K);
    cudaGetSymbolAddress((void**)&Vd, g_V);
    cudaGetSymbolAddress((void**)&Ld, g_L);

    dim3 thr(256);

    // Q' = roi_feat @ Wq^T + Wq_b + u   (u folds the global content bias: aff=(q+u)·k)
    gemm_nt_kernel<<<dim3(FF / 64, NN / 64, 1), thr>>>(
        roi_feat, FF, 0, Wq_w, FF, 0, Qd, FF, 0, FF, 1.f, Wq_b, u);
    // K = ref_feat @ Wk^T + Wk_b
    gemm_nt_kernel<<<dim3(FF / 64, MM / 64, 1), thr>>>(
        ref_feat, FF, 0, Wk_w, FF, 0, Kd, FF, 0, FF, 1.f, Wk_b, nullptr);
    // V = ref_feat @ Wv^T + Wv_b   (Wv_b folds exactly: softmax rows sum to 1)
    gemm_nt_kernel<<<dim3(FF / 64, MM / 64, 1), thr>>>(
        ref_feat, FF, 0, Wv_w, FF, 0, Vd, FF, 0, FF, 1.f, Wv_b, nullptr);
    // L[n,g,m] = 0.125 * Q'[n,g,:]·K[m,g,:]   (batched over g)
    gemm_nt_kernel<<<dim3(MM / 64, NN / 64, GG), thr>>>(
        Qd, FF, DD, Kd, FF, DD, Ld, GG * MM, MM, DD, 0.125f, nullptr, nullptr);
    // L += log(relu(Wg·emb + b) + 1e-6)
    pos_logits_kernel<<<dim3(MM / 256, NN), thr>>>(bbox, ref_bbox, Wg_w, Wg_b);
    // softmax over m
    softmax_kernel<<<NN * GG, thr>>>();
    // out[n, g*64+d] = sum_m attn[n,g,m] * V[m, g*64+d]   (split-k=4, atomic)
    cudaMemsetAsync(out, 0, (size_t)NN * FF * sizeof(float));
    gemm_nn_atomic_kernel<<<dim3(NN / 64, 4, GG), thr>>>(
        Ld, GG * MM, MM, Vd, FF, DD, out, FF, DD, MM / 4);
}

// round 2
// speedup vs baseline: 1.8623x; 1.8623x over previous
#include <cuda_runtime.h>
#include <cstdint>
#include <cstddef>

#define NN 512
#define MM 2048
#define FF 1024
#define GG 16
#define DD 64

// -------- scratch ----------------------------------------------------------
__device__ float g_Q[NN * FF];                 // Q' = roi@Wq^T + Wq_b + u   [n][g*64+d]
__device__ float g_K[MM * FF];                 // K  = ref@Wk^T + Wk_b       [m][g*64+d]
__device__ float g_VT[FF * MM];                // V^T = Wv@ref^T + Wv_b      [g*64+d][m]
__device__ float g_L[(size_t)NN * GG * MM];    // logits / attn              [n][g][m]

__constant__ float c_freq[8] = {
    100.0f,        42.16965034f, 17.78279410f, 7.498942093f,
    3.162277660f,  1.333521432f, 0.5623413252f, 0.2371373706f};

__device__ __forceinline__ uint32_t f2tf32(float f) {
    uint32_t u;
    asm("cvt.rna.tf32.f32 %0, %1;" : "=r"(u) : "f"(f));
    return u;
}

__device__ __forceinline__ void mma_tf32(float* c, const uint32_t* a, const uint32_t* b) {
    asm volatile(
        "mma.sync.aligned.m16n8k8.row.col.f32.tf32.tf32.f32 "
        "{%0,%1,%2,%3}, {%4,%5,%6,%7}, {%8,%9}, {%0,%1,%2,%3};"
        : "+f"(c[0]), "+f"(c[1]), "+f"(c[2]), "+f"(c[3])
        : "r"(a[0]), "r"(a[1]), "r"(a[2]), "r"(a[3]), "r"(b[0]), "r"(b[1]));
}

// ===========================================================================
// C[i,j] (+)= alpha * sum_k A[i,k]*B[j,k]  + cb0[j] + cb1[j] + rbias[i]
// A,B row-major k-contiguous (NT). Block 128 x BN, BK=16, 256 threads,
// tf32 tensor-core mma, fragment-major swizzled smem, double buffered.
// Batched over blockIdx.z with element strides; split-k via nSplit+ATOMIC.
// ===========================================================================
template<int BN, bool ATOMIC>
__global__ void __launch_bounds__(256) mma_nt_kernel(
    const float* __restrict__ A, int lda, int bsA,
    const float* __restrict__ B, int ldb, int bsB,
    float* __restrict__ C, int ldc, int bsC,
    int Kchunk, int nSplit, float alpha,
    const float* __restrict__ cb0, const float* __restrict__ cb1,
    const float* __restrict__ rbias)
{
    constexpr int WARPS_N = BN / 32;        // 4 or 2
    constexpr int WARPS_M = 8 / WARPS_N;    // 2 or 4
    constexpr int MT = (128 / WARPS_M) / 16;// m16 tiles per warp: 4 or 2
    constexpr int LB = BN / 64;             // B float4 loads per thread: 2 or 1

    __shared__ uint32_t sA[2][128 * 16];
    __shared__ uint32_t sB[2][BN * 16];

    const int t = threadIdx.x;
    const int w = t >> 5, lane = t & 31;
    const int g = lane >> 2, tig = lane & 3;
    const int wm = w % WARPS_M, wn = w / WARPS_M;

    const int z = blockIdx.z;
    const int batch = z / nSplit, sp = z - batch * nSplit;
    const float* Ab = A + (size_t)batch * bsA + (size_t)sp * Kchunk;
    const float* Bb = B + (size_t)batch * bsB + (size_t)sp * Kchunk;
    float* Cb = C + (size_t)batch * bsC;
    const int i0 = blockIdx.y * 128, j0 = blockIdx.x * BN;

    // ---- loader precompute (gmem ptr + swizzled smem index per float4) ----
    const float* aPtr[2]; int aIdx[2];
#pragma unroll
    for (int ia = 0; ia < 2; ia++) {
        int fidx = ia * 256 + t;
        int m = fidx >> 2, kq = fidx & 3;
        int ks = kq >> 1, kh = kq & 1;
        int slot = ((m >> 3) & 1) + 2 * kh;
        int tm = m >> 4, gg = m & 7;
        aPtr[ia] = Ab + (size_t)(i0 + m) * lda + kq * 4;
        aIdx[ia] = ((tm * 2 + ks) * 4 + slot) * 32 + ((gg ^ (slot + 4 * ks)) << 2);
    }
    const float* bPtr[LB]; int bIdx[LB];
#pragma unroll
    for (int ib = 0; ib < LB; ib++) {
        int fidx = ib * 256 + t;
        int n = fidx >> 2, kq = fidx & 3;
        int ks = kq >> 1, slot = kq & 1;
        int tn = n >> 3, gg = n & 7;
        bPtr[ib] = Bb + (size_t)(j0 + n) * ldb + kq * 4;
        bIdx[ib] = ((tn * 2 + ks) * 2 + slot) * 32 + ((gg ^ (slot * 4 + ks * 2)) << 2);
    }

    float acc[MT][4][4];
#pragma unroll
    for (int a = 0; a < MT; a++)
#pragma unroll
        for (int b = 0; b < 4; b++)
#pragma unroll
            for (int c = 0; c < 4; c++) acc[a][b][c] = 0.f;

    const int KT = Kchunk / 16;
    float4 ra[2], rb[LB];

    // prologue: tile 0
#pragma unroll
    for (int ia = 0; ia < 2; ia++) ra[ia] = *(const float4*)(aPtr[ia]);
#pragma unroll
    for (int ib = 0; ib < LB; ib++) rb[ib] = *(const float4*)(bPtr[ib]);
#pragma unroll
    for (int ia = 0; ia < 2; ia++)
        *(uint4*)&sA[0][aIdx[ia]] = make_uint4(f2tf32(ra[ia].x), f2tf32(ra[ia].y),
                                               f2tf32(ra[ia].z), f2tf32(ra[ia].w));
#pragma unroll
    for (int ib = 0; ib < LB; ib++)
        *(uint4*)&sB[0][bIdx[ib]] = make_uint4(f2tf32(rb[ib].x), f2tf32(rb[ib].y),
                                               f2tf32(rb[ib].z), f2tf32(rb[ib].w));
    __syncthreads();

    for (int kt = 0; kt < KT; kt++) {
        const int cur = kt & 1;
        if (kt + 1 < KT) {
#pragma unroll
            for (int ia = 0; ia < 2; ia++) ra[ia] = *(const float4*)(aPtr[ia] + (kt + 1) * 16);
#pragma unroll
            for (int ib = 0; ib < LB; ib++) rb[ib] = *(const float4*)(bPtr[ib] + (kt + 1) * 16);
        }
        // ---- compute on buffer cur ----
#pragma unroll
        for (int ks = 0; ks < 2; ks++) {
            uint32_t af[MT][4], bf[4][2];
#pragma unroll
            for (int tn = 0; tn < 4; tn++) {
                int tng = wn * 4 + tn;
                int base = ((tng * 2 + ks) * 2) * 32;
                bf[tn][0] = sB[cur][base + ((g ^ (ks * 2)) << 2) + tig];
                bf[tn][1] = sB[cur][base + 32 + ((g ^ (4 + ks * 2)) << 2) + tig];
            }
#pragma unroll
            for (int tm = 0; tm < MT; tm++) {
                int tmg = wm * MT + tm;
                int base = ((tmg * 2 + ks) * 4) * 32;
#pragma unroll
                for (int s = 0; s < 4; s++)
                    af[tm][s] = sA[cur][base + s * 32 + ((g ^ (s + 4 * ks)) << 2) + tig];
            }
#pragma unroll
            for (int tm = 0; tm < MT; tm++)
#pragma unroll
                for (int tn = 0; tn < 4; tn++)
                    mma_tf32(acc[tm][tn], af[tm], bf[tn]);
        }
        if (kt + 1 < KT) {
            const int nxt = cur ^ 1;
#pragma unroll
            for (int ia = 0; ia < 2; ia++)
                *(uint4*)&sA[nxt][aIdx[ia]] = make_uint4(f2tf32(ra[ia].x), f2tf32(ra[ia].y),
                                                         f2tf32(ra[ia].z), f2tf32(ra[ia].w));
#pragma unroll
            for (int ib = 0; ib < LB; ib++)
                *(uint4*)&sB[nxt][bIdx[ib]] = make_uint4(f2tf32(rb[ib].x), f2tf32(rb[ib].y),
                                                         f2tf32(rb[ib].z), f2tf32(rb[ib].w));
        }
        __syncthreads();
    }

    // ---- epilogue ----
#pragma unroll
    for (int tm = 0; tm < MT; tm++) {
        int r = i0 + wm * (MT * 16) + tm * 16 + g;
        float rb0 = rbias ? rbias[r] : 0.f;
        float rb1 = rbias ? rbias[r + 8] : 0.f;
#pragma unroll
        for (int tn = 0; tn < 4; tn++) {
            int c = j0 + wn * 32 + tn * 8 + tig * 2;
            float b0 = 0.f, b1 = 0.f;
            if (cb0) { b0 += cb0[c]; b1 += cb0[c + 1]; }
            if (cb1) { b0 += cb1[c]; b1 += cb1[c + 1]; }
            float v0 = acc[tm][tn][0] * alpha + b0 + rb0;
            float v1 = acc[tm][tn][1] * alpha + b1 + rb0;
            float v2 = acc[tm][tn][2] * alpha + b0 + rb1;
            float v3 = acc[tm][tn][3] * alpha + b1 + rb1;
            if (ATOMIC) {
                atomicAdd(Cb + (size_t)r * ldc + c, v0);
                atomicAdd(Cb + (size_t)r * ldc + c + 1, v1);
                atomicAdd(Cb + (size_t)(r + 8) * ldc + c, v2);
                atomicAdd(Cb + (size_t)(r + 8) * ldc + c + 1, v3);
            } else {
                *(float2*)(Cb + (size_t)r * ldc + c) = make_float2(v0, v1);
                *(float2*)(Cb + (size_t)(r + 8) * ldc + c) = make_float2(v2, v3);
            }
        }
    }
}

// ===========================================================================
// pos embedding + Wg + relu + log, added onto scaled affinity in g_L.
// ===========================================================================
__global__ void __launch_bounds__(256) pos_logits_kernel(
    const float* __restrict__ bbox, const float* __restrict__ ref_bbox,
    const float* __restrict__ Wg_w, const float* __restrict__ Wg_b)
{
    __shared__ float sWsin[32][16];
    __shared__ float sWcos[32][16];
    __shared__ float sWb[16];
    const int t = threadIdx.x;
    for (int idx = t; idx < 512; idx += 256) {
        int g = idx & 15;
        int cf = idx >> 4;
        int c = cf >> 3, f = cf & 7;
        sWsin[cf][g] = Wg_w[g * 64 + c * 16 + f];
        sWcos[cf][g] = Wg_w[g * 64 + c * 16 + 8 + f];
    }
    if (t < 16) sWb[t] = Wg_b[t];
    __syncthreads();

    const int n = blockIdx.y;
    const int m = blockIdx.x * 256 + t;

    float x0 = bbox[n * 4 + 0], y0 = bbox[n * 4 + 1];
    float x1 = bbox[n * 4 + 2], y1 = bbox[n * 4 + 3];
    float w = x1 - x0 + 1.f, h = y1 - y0 + 1.f;
    float cx = 0.5f * (x0 + x1), cy = 0.5f * (y0 + y1);
    float iw = 1.f / w, ih = 1.f / h;
    float lw = __logf(w), lh = __logf(h);

    float4 rbx = *(const float4*)(ref_bbox + (size_t)m * 4);
    float wr = rbx.z - rbx.x + 1.f, hr = rbx.w - rbx.y + 1.f;
    float cxr = 0.5f * (rbx.x + rbx.z), cyr = 0.5f * (rbx.y + rbx.w);

    float p[4];
    p[0] = __logf(fabsf((cx - cxr) * iw) + 1e-3f);
    p[1] = __logf(fabsf((cy - cyr) * ih) + 1e-3f);
    p[2] = lw - __logf(wr);
    p[3] = lh - __logf(hr);

    float acc[16];
#pragma unroll
    for (int g = 0; g < 16; g++) acc[g] = 0.f;

#pragma unroll
    for (int c = 0; c < 4; c++) {
#pragma unroll
        for (int f = 0; f < 8; f++) {
            float ang = p[c] * c_freq[f];
            float s = __sinf(ang);
            float co = __cosf(ang);
            const int cf = c * 8 + f;
#pragma unroll
            for (int g = 0; g < 16; g += 4) {
                float4 ws = *(const float4*)&sWsin[cf][g];
                float4 wc = *(const float4*)&sWcos[cf][g];
                acc[g + 0] = fmaf(s, ws.x, fmaf(co, wc.x, acc[g + 0]));
                acc[g + 1] = fmaf(s, ws.y, fmaf(co, wc.y, acc[g + 1]));
                acc[g + 2] = fmaf(s, ws.z, fmaf(co, wc.z, acc[g + 2]));
                acc[g + 3] = fmaf(s, ws.w, fmaf(co, wc.w, acc[g + 3]));
            }
        }
    }

    float* Lrow = g_L + (size_t)n * GG * MM + m;
#pragma unroll
    for (int g = 0; g < 16; g++) {
        float val = fmaxf(acc[g] + sWb[g], 0.f);
        float aff = Lrow[(size_t)g * MM];
        Lrow[(size_t)g * MM] = __logf(val + 1e-6f) + aff;
    }
}

// ===========================================================================
__global__ void __launch_bounds__(256) softmax_kernel()
{
    __shared__ float red[8];
    const int t = threadIdx.x;
    float* Lr = g_L + (size_t)blockIdx.x * MM;

    float v[8];
    float mx = -1e30f;
#pragma unroll
    for (int i = 0; i < 8; i++) {
        v[i] = Lr[t + i * 256];
        mx = fmaxf(mx, v[i]);
    }
#pragma unroll
    for (int o = 16; o > 0; o >>= 1) mx = fmaxf(mx, __shfl_xor_sync(~0u, mx, o));
    if ((t & 31) == 0) red[t >> 5] = mx;
    __syncthreads();
    float bm = red[0];
#pragma unroll
    for (int i = 1; i < 8; i++) bm = fmaxf(bm, red[i]);
    __syncthreads();

    float sum = 0.f;
#pragma unroll
    for (int i = 0; i < 8; i++) {
        v[i] = __expf(v[i] - bm);
        sum += v[i];
    }
#pragma unroll
    for (int o = 16; o > 0; o >>= 1) sum += __shfl_xor_sync(~0u, sum, o);
    if ((t & 31) == 0) red[t >> 5] = sum;
    __syncthreads();
    float bs = 0.f;
#pragma unroll
    for (int i = 0; i < 8; i++) bs += red[i];
    float inv = 1.f / bs;
#pragma unroll
    for (int i = 0; i < 8; i++) Lr[t + i * 256] = v[i] * inv;
}

// ===========================================================================
extern "C" void kernel_launch(void* const* d_in, const int* in_sizes, int n_in,
                              void* d_out, int out_size)
{
    (void)in_sizes; (void)n_in; (void)out_size;
    const float* bbox     = (const float*)d_in[0];
    const float* ref_bbox = (const float*)d_in[1];
    const float* roi_feat = (const float*)d_in[2];
    const float* ref_feat = (const float*)d_in[3];
    const float* Wg_w     = (const float*)d_in[4];
    const float* Wg_b     = (const float*)d_in[5];
    const float* Wq_w     = (const float*)d_in[6];
    const float* Wq_b     = (const float*)d_in[7];
    const float* Wk_w     = (const float*)d_in[8];
    const float* Wk_b     = (const float*)d_in[9];
    const float* Wv_w     = (const float*)d_in[10];  // [16,64,1024] == [1024,1024]
    const float* Wv_b     = (const float*)d_in[11];
    const float* u        = (const float*)d_in[12];  // [16,1,64] == [1024]
    float* out = (float*)d_out;

    float *Qd, *Kd, *VTd, *Ld;
    cudaGetSymbolAddress((void**)&Qd, g_Q);
    cudaGetSymbolAddress((void**)&Kd, g_K);
    cudaGetSymbolAddress((void**)&VTd, g_VT);
    cudaGetSymbolAddress((void**)&Ld, g_L);

    dim3 thr(256);

    // Q' = roi_feat @ Wq^T + Wq_b + u  (u folds global content bias)
    mma_nt_kernel<128, false><<<dim3(FF / 128, NN / 128, 1), thr>>>(
        roi_feat, FF, 0, Wq_w, FF, 0, Qd, FF, 0, FF, 1, 1.f, Wq_b, u, nullptr);
    // K = ref_feat @ Wk^T + Wk_b
    mma_nt_kernel<128, false><<<dim3(FF / 128, MM / 128, 1), thr>>>(
        ref_feat, FF, 0, Wk_w, FF, 0, Kd, FF, 0, FF, 1, 1.f, Wk_b, nullptr, nullptr);
    // V^T = Wv @ ref_feat^T, Wv_b as ROW bias (folds exactly; softmax rows sum to 1)
    mma_nt_kernel<128, false><<<dim3(MM / 128, FF / 128, 1), thr>>>(
        Wv_w, FF, 0, ref_feat, FF, 0, VTd, MM, 0, FF, 1, 1.f, nullptr, nullptr, Wv_b);
    // L[n,g,m] = 0.125 * Q'[n,g,:]·K[m,g,:]
    mma_nt_kernel<128, false><<<dim3(MM / 128, NN / 128, GG), thr>>>(
        Qd, FF, DD, Kd, FF, DD, Ld, GG * MM, MM, DD, 1, 0.125f, nullptr, nullptr, nullptr);
    // L += log(relu(Wg·emb + b) + 1e-6)
    pos_logits_kernel<<<dim3(MM / 256, NN), thr>>>(bbox, ref_bbox, Wg_w, Wg_b);
    // softmax over m
    softmax_kernel<<<NN * GG, thr>>>();
    // out[n, g*64+f] = sum_m attn[n,g,m] * VT[g*64+f, m]  (split-k=4, atomic)
    cudaMemsetAsync(out, 0, (size_t)NN * FF * sizeof(float));
    mma_nt_kernel<64, true><<<dim3(1, NN / 128, GG * 4), thr>>>(
        Ld, GG * MM, MM, VTd, MM, DD * MM, out, FF, DD, MM / 4, 4, 1.f,
        nullptr, nullptr, nullptr);
}